// round 1
// baseline (speedup 1.0000x reference)
#include <cuda_runtime.h>
#include <cuda_bf16.h>
#include <math.h>

#define B_  8
#define SQ_ 2048
#define SK_ 2048
#define D_  1024
#define DV_ 1024
#define SCALE (1.0f/32.0f)

// ---------------------------------------------------------------------------
// Kernel 1: raw scores S = (Q @ K^T) * scale, written into the weights slab.
// 64x64 tile per block, BK=16, 256 threads, 4x4 micro-tile per thread.
// Tiles fully masked by causal/length constraints are skipped (softmax kernel
// writes zeros there, so leftover poison in those positions is never read).
// ---------------------------------------------------------------------------
__global__ __launch_bounds__(256) void scores_kernel(
    const float* __restrict__ Q, const float* __restrict__ K,
    const int* __restrict__ qlens, const int* __restrict__ klens,
    float* __restrict__ Sout)
{
    const int b  = blockIdx.z;
    const int q0 = blockIdx.y * 64;
    const int k0 = blockIdx.x * 64;
    const int qlen = qlens[b];
    const int klen = klens[b];
    // skip fully-masked tiles
    if (q0 >= qlen || k0 >= klen || k0 > q0 + 63) return;

    __shared__ float As[16][68];
    __shared__ float Bs[16][68];

    const int tid = threadIdx.x;
    const int tx = tid & 15;       // 0..15 -> cols (k dim of tile)
    const int ty = tid >> 4;       // 0..15 -> rows (q dim of tile)
    const int lrow = tid >> 2;     // 0..63 loader row
    const int lcol = (tid & 3) * 4;// 0,4,8,12 loader col

    const float* Qb = Q + ((size_t)b * SQ_ + q0) * D_;
    const float* Kb = K + ((size_t)b * SK_ + k0) * D_;

    float acc[4][4];
#pragma unroll
    for (int i = 0; i < 4; ++i)
#pragma unroll
        for (int j = 0; j < 4; ++j) acc[i][j] = 0.f;

    for (int kk = 0; kk < D_; kk += 16) {
        float4 qa = *(const float4*)(Qb + (size_t)lrow * D_ + kk + lcol);
        float4 kb = *(const float4*)(Kb + (size_t)lrow * D_ + kk + lcol);
        As[lcol+0][lrow] = qa.x; As[lcol+1][lrow] = qa.y;
        As[lcol+2][lrow] = qa.z; As[lcol+3][lrow] = qa.w;
        Bs[lcol+0][lrow] = kb.x; Bs[lcol+1][lrow] = kb.y;
        Bs[lcol+2][lrow] = kb.z; Bs[lcol+3][lrow] = kb.w;
        __syncthreads();
#pragma unroll
        for (int p = 0; p < 16; ++p) {
            float4 a = *(const float4*)&As[p][ty * 4];
            float4 bv = *(const float4*)&Bs[p][tx * 4];
            acc[0][0] += a.x * bv.x; acc[0][1] += a.x * bv.y;
            acc[0][2] += a.x * bv.z; acc[0][3] += a.x * bv.w;
            acc[1][0] += a.y * bv.x; acc[1][1] += a.y * bv.y;
            acc[1][2] += a.y * bv.z; acc[1][3] += a.y * bv.w;
            acc[2][0] += a.z * bv.x; acc[2][1] += a.z * bv.y;
            acc[2][2] += a.z * bv.z; acc[2][3] += a.z * bv.w;
            acc[3][0] += a.w * bv.x; acc[3][1] += a.w * bv.y;
            acc[3][2] += a.w * bv.z; acc[3][3] += a.w * bv.w;
        }
        __syncthreads();
    }

    float* Srow = Sout + ((size_t)b * SQ_ + q0) * SK_ + k0;
#pragma unroll
    for (int i = 0; i < 4; ++i) {
        float4 o;
        o.x = acc[i][0] * SCALE; o.y = acc[i][1] * SCALE;
        o.z = acc[i][2] * SCALE; o.w = acc[i][3] * SCALE;
        *(float4*)(Srow + (size_t)(ty * 4 + i) * SK_ + tx * 4) = o;
    }
}

// ---------------------------------------------------------------------------
// Kernel 2: in-place masked softmax on each (b, q) row of the weights slab.
// One 256-thread block per row. Writes exact zeros outside the valid prefix
// and full-zero rows for q >= qlen (matches reference NaN->0 semantics).
// ---------------------------------------------------------------------------
__global__ __launch_bounds__(256) void softmax_kernel(
    float* __restrict__ Wio,
    const int* __restrict__ qlens, const int* __restrict__ klens)
{
    const int q = blockIdx.x;
    const int b = blockIdx.y;
    const int tid = threadIdx.x;
    float* row = Wio + ((size_t)b * SQ_ + q) * SK_;

    const int qlen = qlens[b];
    const int klen = klens[b];

    if (q >= qlen) {
        float4 z = make_float4(0.f, 0.f, 0.f, 0.f);
        for (int j = tid; j < SK_ / 4; j += 256) ((float4*)row)[j] = z;
        return;
    }

    const int kk = min(klen, q + 1);   // valid prefix length (>= 1)

    __shared__ float buf[SK_];
    __shared__ float red[256];

    // load row to smem, masked max
    float m = -3.402823466e38f;
    for (int j = tid; j < SK_ / 4; j += 256) {
        float4 s = ((const float4*)row)[j];
        ((float4*)buf)[j] = s;
        int base = j * 4;
        if (base + 0 < kk) m = fmaxf(m, s.x);
        if (base + 1 < kk) m = fmaxf(m, s.y);
        if (base + 2 < kk) m = fmaxf(m, s.z);
        if (base + 3 < kk) m = fmaxf(m, s.w);
    }
    red[tid] = m; __syncthreads();
    for (int off = 128; off > 0; off >>= 1) {
        if (tid < off) red[tid] = fmaxf(red[tid], red[tid + off]);
        __syncthreads();
    }
    m = red[0]; __syncthreads();

    // exp + sum
    float sum = 0.f;
    for (int j = tid; j < SK_ / 4; j += 256) {
        int base = j * 4;
        float4 s = ((const float4*)buf)[j];
        float4 e;
        e.x = (base + 0 < kk) ? __expf(s.x - m) : 0.f;
        e.y = (base + 1 < kk) ? __expf(s.y - m) : 0.f;
        e.z = (base + 2 < kk) ? __expf(s.z - m) : 0.f;
        e.w = (base + 3 < kk) ? __expf(s.w - m) : 0.f;
        ((float4*)buf)[j] = e;
        sum += e.x + e.y + e.z + e.w;
    }
    red[tid] = sum; __syncthreads();
    for (int off = 128; off > 0; off >>= 1) {
        if (tid < off) red[tid] += red[tid + off];
        __syncthreads();
    }
    const float inv = 1.f / red[0];

    // normalize + writeback
    for (int j = tid; j < SK_ / 4; j += 256) {
        float4 e = ((const float4*)buf)[j];
        e.x *= inv; e.y *= inv; e.z *= inv; e.w *= inv;
        ((float4*)row)[j] = e;
    }
}

// ---------------------------------------------------------------------------
// Kernel 3: context = W @ V. 64x64 tile, BK=16. K-loop clamped to the valid
// prefix (weights are exact zeros beyond it, clamp is perf-only).
// ---------------------------------------------------------------------------
__global__ __launch_bounds__(256) void context_kernel(
    const float* __restrict__ W, const float* __restrict__ V,
    const int* __restrict__ qlens, const int* __restrict__ klens,
    float* __restrict__ C)
{
    const int b  = blockIdx.z;
    const int q0 = blockIdx.y * 64;
    const int v0 = blockIdx.x * 64;
    const int qlen = qlens[b];
    const int klen = klens[b];

    const int tid = threadIdx.x;
    const int tx = tid & 15;
    const int ty = tid >> 4;

    float* Cb = C + ((size_t)b * SQ_ + q0) * DV_ + v0;

    if (q0 >= qlen) {   // whole tile of rows masked -> zero context
        float4 z = make_float4(0.f, 0.f, 0.f, 0.f);
#pragma unroll
        for (int i = 0; i < 4; ++i)
            *(float4*)(Cb + (size_t)(ty * 4 + i) * DV_ + tx * 4) = z;
        return;
    }

    __shared__ float As[16][68];
    __shared__ float Bs[16][68];

    const int lrowA = tid >> 2;        // 0..63 (q)
    const int lcolA = (tid & 3) * 4;   // k within slab
    const int lrowB = tid >> 4;        // 0..15 (k)
    const int lcolB = (tid & 15) * 4;  // v within tile

    const float* Wb = W + ((size_t)b * SQ_ + q0) * SK_;
    const float* Vb = V + (size_t)b * SK_ * DV_ + v0;

    float acc[4][4];
#pragma unroll
    for (int i = 0; i < 4; ++i)
#pragma unroll
        for (int j = 0; j < 4; ++j) acc[i][j] = 0.f;

    const int kend  = min(klen, q0 + 64);
    const int kstop = (kend + 15) & ~15;   // round up; weights there are zeros

    for (int kk = 0; kk < kstop; kk += 16) {
        float4 wa = *(const float4*)(Wb + (size_t)lrowA * SK_ + kk + lcolA);
        As[lcolA+0][lrowA] = wa.x; As[lcolA+1][lrowA] = wa.y;
        As[lcolA+2][lrowA] = wa.z; As[lcolA+3][lrowA] = wa.w;
        float4 vb = *(const float4*)(Vb + (size_t)(kk + lrowB) * DV_ + lcolB);
        *(float4*)&Bs[lrowB][lcolB] = vb;
        __syncthreads();
#pragma unroll
        for (int p = 0; p < 16; ++p) {
            float4 a = *(const float4*)&As[p][ty * 4];
            float4 bv = *(const float4*)&Bs[p][tx * 4];
            acc[0][0] += a.x * bv.x; acc[0][1] += a.x * bv.y;
            acc[0][2] += a.x * bv.z; acc[0][3] += a.x * bv.w;
            acc[1][0] += a.y * bv.x; acc[1][1] += a.y * bv.y;
            acc[1][2] += a.y * bv.z; acc[1][3] += a.y * bv.w;
            acc[2][0] += a.z * bv.x; acc[2][1] += a.z * bv.y;
            acc[2][2] += a.z * bv.z; acc[2][3] += a.z * bv.w;
            acc[3][0] += a.w * bv.x; acc[3][1] += a.w * bv.y;
            acc[3][2] += a.w * bv.z; acc[3][3] += a.w * bv.w;
        }
        __syncthreads();
    }

#pragma unroll
    for (int i = 0; i < 4; ++i) {
        float4 o;
        o.x = acc[i][0]; o.y = acc[i][1]; o.z = acc[i][2]; o.w = acc[i][3];
        *(float4*)(Cb + (size_t)(ty * 4 + i) * DV_ + tx * 4) = o;
    }
}

// ---------------------------------------------------------------------------
extern "C" void kernel_launch(void* const* d_in, const int* in_sizes, int n_in,
                              void* d_out, int out_size)
{
    const float* Q = (const float*)d_in[0];
    const float* K = (const float*)d_in[1];
    const float* V = (const float*)d_in[2];
    const int* qlens = (const int*)d_in[3];
    const int* klens = (const int*)d_in[4];

    float* ctx = (float*)d_out;                                   // (B,SQ,DV)
    float* wts = (float*)d_out + (size_t)B_ * SQ_ * DV_;          // (B,SQ,SK)

    // 1) raw scaled scores into the weights slab (masked tiles skipped)
    {
        dim3 grid(SK_ / 64, SQ_ / 64, B_);
        scores_kernel<<<grid, 256>>>(Q, K, qlens, klens, wts);
    }
    // 2) in-place masked softmax (also zero-fills all masked positions)
    {
        dim3 grid(SQ_, B_);
        softmax_kernel<<<grid, 256>>>(wts, qlens, klens);
    }
    // 3) context = W @ V
    {
        dim3 grid(DV_ / 64, SQ_ / 64, B_);
        context_kernel<<<grid, 256>>>(wts, V, qlens, klens, ctx);
    }
}